// round 3
// baseline (speedup 1.0000x reference)
#include <cuda_runtime.h>
#include <cuda_bf16.h>
#include <stdint.h>
#include <math.h>

// Problem constants
#define Bz  2
#define Sq  2048
#define Dm  1024
#define Hn  16
#define DHd 64
#define BH  (Bz * Hn)

#define NIN ((size_t)Bz * Sq * Dm)    // 4194304 (inputs / ctx)
#define NW  ((size_t)Dm * Dm)         // 1048576 (one weight)
#define NQ  ((size_t)BH * Sq * DHd)   // 4194304 (q/k/v split-head)
#define CLOG2E 1.4426950408889634f

// ---------------------------------------------------------------------------
// Scratch (allocation-free __device__ globals), all pre-split bf16 hi/lo
// ---------------------------------------------------------------------------
__device__ __align__(256) __nv_bfloat16 g_inh[3 * NIN], g_inl[3 * NIN];
__device__ __align__(256) __nv_bfloat16 g_wh[4 * NW],  g_wl[4 * NW];
__device__ __align__(256) __nv_bfloat16 g_qh[NQ], g_ql[NQ];
__device__ __align__(256) __nv_bfloat16 g_kh[NQ], g_kl[NQ];
__device__ __align__(256) __nv_bfloat16 g_vh[NQ], g_vl[NQ];
__device__ __align__(256) __nv_bfloat16 g_ch[NIN], g_cl[NIN];
__device__ float g_croff[(size_t)BH * Sq];
__device__ int   g_mask_is_int;

// ---------------------------------------------------------------------------
// Helpers
// ---------------------------------------------------------------------------
__device__ __forceinline__ uint32_t smem_u32(const void* p) {
    return (uint32_t)__cvta_generic_to_shared(p);
}
__device__ __forceinline__ void ldm4(uint32_t* r, uint32_t a) {
    asm volatile("ldmatrix.sync.aligned.m8n8.x4.shared.b16 {%0,%1,%2,%3},[%4];"
                 : "=r"(r[0]), "=r"(r[1]), "=r"(r[2]), "=r"(r[3]) : "r"(a));
}
__device__ __forceinline__ void ldm4t(uint32_t* r, uint32_t a) {
    asm volatile("ldmatrix.sync.aligned.m8n8.x4.trans.shared.b16 {%0,%1,%2,%3},[%4];"
                 : "=r"(r[0]), "=r"(r[1]), "=r"(r[2]), "=r"(r[3]) : "r"(a));
}
__device__ __forceinline__ void mma_bf16(float* c, const uint32_t* a, const uint32_t* b) {
    asm volatile(
        "mma.sync.aligned.m16n8k16.row.col.f32.bf16.bf16.f32 "
        "{%0,%1,%2,%3},{%4,%5,%6,%7},{%8,%9},{%0,%1,%2,%3};"
        : "+f"(c[0]), "+f"(c[1]), "+f"(c[2]), "+f"(c[3])
        : "r"(a[0]), "r"(a[1]), "r"(a[2]), "r"(a[3]), "r"(b[0]), "r"(b[1]));
}
__device__ __forceinline__ void split1(float x, __nv_bfloat16& h, __nv_bfloat16& l) {
    h = __float2bfloat16(x);
    l = __float2bfloat16(x - __bfloat162float(h));
}
__device__ __forceinline__ float ex2(float x) {
    float y; asm("ex2.approx.f32 %0,%1;" : "=f"(y) : "f"(x)); return y;
}
__device__ __forceinline__ float lg2(float x) {
    float y; asm("lg2.approx.f32 %0,%1;" : "=f"(y) : "f"(x)); return y;
}
// online (max, expsum) merge in exp2 domain; -inf safe
__device__ __forceinline__ void merge_ms(float& m, float& s, float om, float os) {
    float nm = fmaxf(m, om);
    if (nm > -INFINITY) {
        float sa = (m  > -INFINITY) ? s  * ex2((m  - nm) * CLOG2E) : 0.f;
        float sb = (om > -INFINITY) ? os * ex2((om - nm) * CLOG2E) : 0.f;
        s = sa + sb;
    }
    m = nm;
}

// ---------------------------------------------------------------------------
// Mask dtype detector (reads only first 4096 bytes; deterministic)
// ---------------------------------------------------------------------------
__global__ void detect_mask_kernel(const unsigned char* __restrict__ m) {
    __shared__ int any;
    if (threadIdx.x == 0) any = 0;
    __syncthreads();
    int local = 0;
    for (int i = threadIdx.x; i < Bz * Sq; i += blockDim.x)
        if ((i & 3) && m[i]) local = 1;
    if (local) atomicOr(&any, 1);
    __syncthreads();
    if (threadIdx.x == 0) g_mask_is_int = (any == 0) ? 1 : 0;
}

// ---------------------------------------------------------------------------
// Pre-split f32 -> (hi, lo) bf16 pairs, vectorized
// ---------------------------------------------------------------------------
__global__ void split_kernel(const float4* __restrict__ src,
                             __nv_bfloat162* __restrict__ dh,
                             __nv_bfloat162* __restrict__ dl, int n4)
{
    int i = blockIdx.x * blockDim.x + threadIdx.x;
    if (i >= n4) return;
    float4 v = src[i];
    __nv_bfloat16 hx, hy, hz, hw, lx, ly, lz, lw;
    split1(v.x, hx, lx); split1(v.y, hy, ly);
    split1(v.z, hz, lz); split1(v.w, hw, lw);
    dh[2 * i]     = __nv_bfloat162{hx, hy};
    dh[2 * i + 1] = __nv_bfloat162{hz, hw};
    dl[2 * i]     = __nv_bfloat162{lx, ly};
    dl[2 * i + 1] = __nv_bfloat162{lz, lw};
}

// ---------------------------------------------------------------------------
// Projection GEMM from pre-split operands. 128x128x32 tiles, 8 warps.
// MODE 0: C = A*W + bias, head-split epilogue -> split bf16 (Ch, Cl)
// MODE 1: C = A*W + bias, plain f32 epilogue -> Cf
// A: [4096][1024] row-major split; B(W): [1024][1024] row-major split (trans).
// ---------------------------------------------------------------------------
template <int MODE>
__global__ void __launch_bounds__(256) proj_gemm(
    const __nv_bfloat16* __restrict__ Ahg, const __nv_bfloat16* __restrict__ Alg,
    const __nv_bfloat16* __restrict__ Bhg, const __nv_bfloat16* __restrict__ Blg,
    const float* __restrict__ bias,
    __nv_bfloat16* __restrict__ Ch, __nv_bfloat16* __restrict__ Cl,
    float* __restrict__ Cf)
{
    constexpr int SA = 40, SB = 136;
    __shared__ __nv_bfloat16 Ah[128 * SA], Al[128 * SA];
    __shared__ __nv_bfloat16 Bh[32 * SB],  Bl[32 * SB];

    const int tid = threadIdx.x, lane = tid & 31, warp = tid >> 5;
    const int wm = (warp >> 2) * 64;
    const int wn = (warp & 3) * 32;
    const int bm = blockIdx.y * 128;
    const int bn = blockIdx.x * 128;

    float acc[4][4][4];
#pragma unroll
    for (int i = 0; i < 4; i++)
#pragma unroll
        for (int j = 0; j < 4; j++)
#pragma unroll
            for (int q = 0; q < 4; q++) acc[i][j][q] = 0.f;

    const uint32_t aH = smem_u32(Ah), aL = smem_u32(Al);
    const uint32_t bH = smem_u32(Bh), bL = smem_u32(Bl);

    for (int k0 = 0; k0 < Dm; k0 += 32) {
#pragma unroll
        for (int r = 0; r < 2; r++) {
            const int idx = tid + r * 256;
            const int m = idx >> 2, c8 = (idx & 3) * 8;
            *(uint4*)&Ah[m * SA + c8] = *(const uint4*)(Ahg + (size_t)(bm + m) * Dm + k0 + c8);
            *(uint4*)&Al[m * SA + c8] = *(const uint4*)(Alg + (size_t)(bm + m) * Dm + k0 + c8);
        }
#pragma unroll
        for (int r = 0; r < 2; r++) {
            const int idx = tid + r * 256;
            const int kr = idx >> 4, n8 = (idx & 15) * 8;
            *(uint4*)&Bh[kr * SB + n8] = *(const uint4*)(Bhg + (size_t)(k0 + kr) * Dm + bn + n8);
            *(uint4*)&Bl[kr * SB + n8] = *(const uint4*)(Blg + (size_t)(k0 + kr) * Dm + bn + n8);
        }
        __syncthreads();

#pragma unroll
        for (int kk = 0; kk < 32; kk += 16) {
            uint32_t ah[4][4], al[4][4];
            const int arow = wm + (lane & 7) + ((lane >> 3) & 1) * 8;
            const int acol = kk + (lane >> 4) * 8;
#pragma unroll
            for (int mt = 0; mt < 4; mt++) {
                const uint32_t off = (uint32_t)(((arow + mt * 16) * SA + acol) * 2);
                ldm4(ah[mt], aH + off);
                ldm4(al[mt], aL + off);
            }
            uint32_t bh[4][2], bl[4][2];
            const int brow = kk + (lane & 7) + ((lane >> 3) & 1) * 8;
#pragma unroll
            for (int sp = 0; sp < 2; sp++) {
                const int bcol = wn + sp * 16 + (lane >> 4) * 8;
                const uint32_t off = (uint32_t)((brow * SB + bcol) * 2);
                uint32_t t[4];
                ldm4t(t, bH + off);
                bh[2 * sp][0] = t[0]; bh[2 * sp][1] = t[1];
                bh[2 * sp + 1][0] = t[2]; bh[2 * sp + 1][1] = t[3];
                ldm4t(t, bL + off);
                bl[2 * sp][0] = t[0]; bl[2 * sp][1] = t[1];
                bl[2 * sp + 1][0] = t[2]; bl[2 * sp + 1][1] = t[3];
            }
#pragma unroll
            for (int mt = 0; mt < 4; mt++)
#pragma unroll
                for (int nt = 0; nt < 4; nt++) {
                    mma_bf16(acc[mt][nt], ah[mt], bh[nt]);
                    mma_bf16(acc[mt][nt], ah[mt], bl[nt]);
                    mma_bf16(acc[mt][nt], al[mt], bh[nt]);
                }
        }
        __syncthreads();
    }

    const int g = lane >> 2, t2 = (lane & 3) * 2;
#pragma unroll
    for (int mt = 0; mt < 4; mt++)
#pragma unroll
        for (int nt = 0; nt < 4; nt++) {
            const int col = bn + wn + nt * 8 + t2;
#pragma unroll
            for (int h2 = 0; h2 < 2; h2++) {
                const int row = bm + wm + mt * 16 + g + h2 * 8;
                float c0 = acc[mt][nt][h2 * 2 + 0] + bias[col];
                float c1 = acc[mt][nt][h2 * 2 + 1] + bias[col + 1];
                if (MODE == 0) {
                    const int bb = row >> 11, ss = row & (Sq - 1);
                    const int hh = col >> 6,  dh = col & (DHd - 1);
                    const size_t o = (((size_t)(bb * Hn + hh)) * Sq + ss) * DHd + dh;
                    __nv_bfloat16 h0, h1, l0, l1;
                    split1(c0, h0, l0); split1(c1, h1, l1);
                    *(__nv_bfloat162*)&Ch[o] = __nv_bfloat162{h0, h1};
                    *(__nv_bfloat162*)&Cl[o] = __nv_bfloat162{l0, l1};
                } else {
                    *(float2*)(Cf + (size_t)row * Dm + col) = make_float2(c0, c1);
                }
            }
        }
}

// ---------------------------------------------------------------------------
// Scores: per (bh, 128-row strip). Q resident in smem; loops 16 col-tiles.
// Writes raw masked/scaled scores (f32) to attn; computes per-row online
// (max, expsum) stats; emits croff[row] = m*log2e + log2(sum).
// ---------------------------------------------------------------------------
__global__ void __launch_bounds__(256) scores_kernel(
    const void* __restrict__ mask, float* __restrict__ attn)
{
    constexpr int SA = 72, SB = 72;
    extern __shared__ char smem[];
    float* smM = (float*)smem;                       // [128][4]
    float* smS = smM + 128 * 4;                      // [128][4]
    __nv_bfloat16* Qh = (__nv_bfloat16*)(smS + 128 * 4);
    __nv_bfloat16* Ql = Qh + 128 * SA;
    __nv_bfloat16* Kh = Ql + 128 * SA;
    __nv_bfloat16* Kl = Kh + 128 * SB;

    const int z = blockIdx.z, zb = z / Hn;
    const int bm = blockIdx.y * 128;
    const __nv_bfloat16* qh = g_qh + (size_t)z * Sq * DHd;
    const __nv_bfloat16* ql = g_ql + (size_t)z * Sq * DHd;
    const __nv_bfloat16* kh = g_kh + (size_t)z * Sq * DHd;
    const __nv_bfloat16* kl = g_kl + (size_t)z * Sq * DHd;

    const int tid = threadIdx.x, lane = tid & 31, warp = tid >> 5;
    const int wm = (warp >> 2) * 64;
    const int wn = (warp & 3) * 32;
    const int g = lane >> 2, t2 = (lane & 3) * 2;
    const int mint = g_mask_is_int;

#pragma unroll
    for (int r = 0; r < 4; r++) {
        const int idx = tid + r * 256;
        const int m = idx >> 3, c8 = (idx & 7) * 8;
        *(uint4*)&Qh[m * SA + c8] = *(const uint4*)(qh + (size_t)(bm + m) * DHd + c8);
        *(uint4*)&Ql[m * SA + c8] = *(const uint4*)(ql + (size_t)(bm + m) * DHd + c8);
    }

    float stm[8], sts[8];
#pragma unroll
    for (int i = 0; i < 8; i++) { stm[i] = -INFINITY; sts[i] = 0.f; }

    const uint32_t aH = smem_u32(Qh), aL = smem_u32(Ql);
    const uint32_t bH = smem_u32(Kh), bL = smem_u32(Kl);

    for (int ct = 0; ct < 16; ct++) {
        const int bn = ct * 128;
#pragma unroll
        for (int r = 0; r < 4; r++) {
            const int idx = tid + r * 256;
            const int m = idx >> 3, c8 = (idx & 7) * 8;
            *(uint4*)&Kh[m * SB + c8] = *(const uint4*)(kh + (size_t)(bn + m) * DHd + c8);
            *(uint4*)&Kl[m * SB + c8] = *(const uint4*)(kl + (size_t)(bn + m) * DHd + c8);
        }
        __syncthreads();

        float acc[4][4][4];
#pragma unroll
        for (int i = 0; i < 4; i++)
#pragma unroll
            for (int j = 0; j < 4; j++)
#pragma unroll
                for (int q = 0; q < 4; q++) acc[i][j][q] = 0.f;

#pragma unroll
        for (int kk = 0; kk < DHd; kk += 16) {
            uint32_t ah[4][4], al[4][4];
            const int arow = wm + (lane & 7) + ((lane >> 3) & 1) * 8;
            const int acol = kk + (lane >> 4) * 8;
#pragma unroll
            for (int mt = 0; mt < 4; mt++) {
                const uint32_t off = (uint32_t)(((arow + mt * 16) * SA + acol) * 2);
                ldm4(ah[mt], aH + off);
                ldm4(al[mt], aL + off);
            }
            uint32_t bh[4][2], bl[4][2];
#pragma unroll
            for (int sp = 0; sp < 2; sp++) {
                const int brow = wn + sp * 16 + (lane & 7) + ((lane >> 3) & 1) * 8;
                const int bcol = kk + (lane >> 4) * 8;
                const uint32_t off = (uint32_t)((brow * SB + bcol) * 2);
                uint32_t t[4];
                ldm4(t, bH + off);
                bh[2 * sp][0] = t[0]; bh[2 * sp + 1][0] = t[1];
                bh[2 * sp][1] = t[2]; bh[2 * sp + 1][1] = t[3];
                ldm4(t, bL + off);
                bl[2 * sp][0] = t[0]; bl[2 * sp + 1][0] = t[1];
                bl[2 * sp][1] = t[2]; bl[2 * sp + 1][1] = t[3];
            }
#pragma unroll
            for (int mt = 0; mt < 4; mt++)
#pragma unroll
                for (int nt = 0; nt < 4; nt++) {
                    mma_bf16(acc[mt][nt], ah[mt], bh[nt]);
                    mma_bf16(acc[mt][nt], ah[mt], bl[nt]);
                    mma_bf16(acc[mt][nt], al[mt], bh[nt]);
                }
        }

        // epilogue: mask+scale, write raw, update online stats
        bool mb[8];
#pragma unroll
        for (int nt = 0; nt < 4; nt++) {
            const int col = bn + wn + nt * 8 + t2;
            if (mint) {
                mb[2 * nt]     = ((const int*)mask)[zb * Sq + col] != 0;
                mb[2 * nt + 1] = ((const int*)mask)[zb * Sq + col + 1] != 0;
            } else {
                mb[2 * nt]     = ((const unsigned char*)mask)[zb * Sq + col] != 0;
                mb[2 * nt + 1] = ((const unsigned char*)mask)[zb * Sq + col + 1] != 0;
            }
        }
#pragma unroll
        for (int mt = 0; mt < 4; mt++)
#pragma unroll
            for (int h2 = 0; h2 < 2; h2++) {
                const int row = bm + wm + mt * 16 + g + h2 * 8;
                float* rp = attn + ((size_t)z * Sq + row) * Sq;
                float v8[8];
                float tm = -INFINITY;
#pragma unroll
                for (int nt = 0; nt < 4; nt++) {
                    float v0 = mb[2 * nt]     ? acc[mt][nt][h2 * 2 + 0] * 0.125f : -INFINITY;
                    float v1 = mb[2 * nt + 1] ? acc[mt][nt][h2 * 2 + 1] * 0.125f : -INFINITY;
                    *(float2*)(rp + bn + wn + nt * 8 + t2) = make_float2(v0, v1);
                    v8[2 * nt] = v0; v8[2 * nt + 1] = v1;
                    tm = fmaxf(tm, fmaxf(v0, v1));
                }
                if (tm > -INFINITY) {
                    float ts = 0.f;
#pragma unroll
                    for (int i = 0; i < 8; i++)
                        ts += ex2((v8[i] - tm) * CLOG2E);
                    merge_ms(stm[mt * 2 + h2], sts[mt * 2 + h2], tm, ts);
                }
            }
        __syncthreads();
    }

    // quad reduce (cols within warp), then cross-warp via smem
#pragma unroll
    for (int o = 1; o <= 2; o <<= 1)
#pragma unroll
        for (int s = 0; s < 8; s++) {
            float om = __shfl_xor_sync(~0u, stm[s], o);
            float os = __shfl_xor_sync(~0u, sts[s], o);
            merge_ms(stm[s], sts[s], om, os);
        }
    if ((lane & 3) == 0) {
#pragma unroll
        for (int mt = 0; mt < 4; mt++)
#pragma unroll
            for (int h2 = 0; h2 < 2; h2++) {
                const int rl = wm + mt * 16 + (lane >> 2) + h2 * 8;
                smM[rl * 4 + (warp & 3)] = stm[mt * 2 + h2];
                smS[rl * 4 + (warp & 3)] = sts[mt * 2 + h2];
            }
    }
    __syncthreads();
    if (tid < 128) {
        float m = -INFINITY, s = 0.f;
#pragma unroll
        for (int j = 0; j < 4; j++)
            merge_ms(m, s, smM[tid * 4 + j], smS[tid * 4 + j]);
        g_croff[(size_t)z * Sq + bm + tid] = fmaf(m, CLOG2E, lg2(s));
    }
}

// ---------------------------------------------------------------------------
// Ctx: per (bh, 128-row strip). Reads raw scores, normalizes on the fly
// (p = ex2(s*log2e - croff)), writes attn in place, splits p to bf16,
// MMA with split V -> ctx written as split bf16 [B,S,D].
// ---------------------------------------------------------------------------
__global__ void __launch_bounds__(256) ctx_kernel(float* __restrict__ attn)
{
    constexpr int SA = 136, SB = 72;
    extern __shared__ char smem[];
    float* crf = (float*)smem;                        // [128]
    __nv_bfloat16* Ph = (__nv_bfloat16*)(smem + 512);
    __nv_bfloat16* Pl = Ph + 128 * SA;
    __nv_bfloat16* Vh = Pl + 128 * SA;
    __nv_bfloat16* Vl = Vh + 128 * SB;

    const int z = blockIdx.z, zb = z / Hn, zh = z % Hn;
    const int bm = blockIdx.y * 128;
    const __nv_bfloat16* vh = g_vh + (size_t)z * Sq * DHd;
    const __nv_bfloat16* vl = g_vl + (size_t)z * Sq * DHd;

    const int tid = threadIdx.x, lane = tid & 31, warp = tid >> 5;
    const int wm = (warp >> 2) * 64;
    const int wn = (warp & 3) * 16;   // N=64, WN=16, NT=2

    if (tid < 128) crf[tid] = g_croff[(size_t)z * Sq + bm + tid];
    __syncthreads();

    float acc[4][2][4];
#pragma unroll
    for (int i = 0; i < 4; i++)
#pragma unroll
        for (int j = 0; j < 2; j++)
#pragma unroll
            for (int q = 0; q < 4; q++) acc[i][j][q] = 0.f;

    const uint32_t aH = smem_u32(Ph), aL = smem_u32(Pl);
    const uint32_t bH = smem_u32(Vh), bL = smem_u32(Vl);

    const int prow  = tid >> 1;
    const int cbase = (tid & 1) * 64;

    for (int kt = 0; kt < 16; kt++) {
        const int k0 = kt * 128;
        // P fill: read raw, normalize, write attn in place, split to smem
        {
            float* rp = attn + ((size_t)z * Sq + bm + prow) * Sq + k0 + cbase;
            const float cr = crf[prow];
#pragma unroll
            for (int i = 0; i < 16; i++) {
                float4 v = *(float4*)(rp + i * 4);
                v.x = ex2(fmaf(v.x, CLOG2E, -cr));
                v.y = ex2(fmaf(v.y, CLOG2E, -cr));
                v.z = ex2(fmaf(v.z, CLOG2E, -cr));
                v.w = ex2(fmaf(v.w, CLOG2E, -cr));
                *(float4*)(rp + i * 4) = v;
                __nv_bfloat16 h0, h1, h2, h3, l0, l1, l2, l3;
                split1(v.x, h0, l0); split1(v.y, h1, l1);
                split1(v.z, h2, l2); split1(v.w, h3, l3);
                const int so = prow * SA + cbase + i * 4;
                *(__nv_bfloat162*)&Ph[so]     = __nv_bfloat162{h0, h1};
                *(__nv_bfloat162*)&Ph[so + 2] = __nv_bfloat162{h2, h3};
                *(__nv_bfloat162*)&Pl[so]     = __nv_bfloat162{l0, l1};
                *(__nv_bfloat162*)&Pl[so + 2] = __nv_bfloat162{l2, l3};
            }
        }
        // V fill (copy)
#pragma unroll
        for (int r = 0; r < 4; r++) {
            const int idx = tid + r * 256;
            const int kr = idx >> 3, n8 = (idx & 7) * 8;
            *(uint4*)&Vh[kr * SB + n8] = *(const uint4*)(vh + (size_t)(k0 + kr) * DHd + n8);
            *(uint4*)&Vl[kr * SB + n8] = *(const uint4*)(vl + (size_t)(k0 + kr) * DHd + n8);
        }
        __syncthreads();

#pragma unroll
        for (int kk = 0; kk < 128; kk += 16) {
            uint32_t ah[4][4], al[4][4];
            const int arow = wm + (lane & 7) + ((lane >> 3) & 1) * 8;
            const int acol = kk + (lane >> 4) * 8;
#pragma unroll
            for (int mt = 0; mt < 4; mt++) {
                const uint32_t off = (uint32_t)(((arow + mt * 16) * SA + acol) * 2);
                ldm4(ah[mt], aH + off);
                ldm4(al[mt], aL + off);
            }
            uint32_t bh[2][2], bl[2][2];
            {
                const int brow = kk + (lane & 7) + ((lane >> 3) & 1) * 8;
                const int bcol = wn + (lane >> 4) * 8;
                const uint32_t off = (uint32_t)((brow * SB + bcol) * 2);
                uint32_t t[4];
                ldm4t(t, bH + off);
                bh[0][0] = t[0]; bh[0][1] = t[1];
                bh[1][0] = t[2]; bh[1][1] = t[3];
                ldm4t(t, bL + off);
                bl[0][0] = t[0]; bl[0][1] = t[1];
                bl[1][0] = t[2]; bl[1][1] = t[3];
            }
#pragma unroll
            for (int mt = 0; mt < 4; mt++)
#pragma unroll
                for (int nt = 0; nt < 2; nt++) {
                    mma_bf16(acc[mt][nt], ah[mt], bh[nt]);
                    mma_bf16(acc[mt][nt], ah[mt], bl[nt]);
                    mma_bf16(acc[mt][nt], al[mt], bh[nt]);
                }
        }
        __syncthreads();
    }

    const int g = lane >> 2, t2 = (lane & 3) * 2;
#pragma unroll
    for (int mt = 0; mt < 4; mt++)
#pragma unroll
        for (int nt = 0; nt < 2; nt++) {
            const int col = wn + nt * 8 + t2;
#pragma unroll
            for (int h2 = 0; h2 < 2; h2++) {
                const int row = bm + wm + mt * 16 + g + h2 * 8;
                const size_t o = ((size_t)zb * Sq + row) * Dm + zh * DHd + col;
                __nv_bfloat16 h0, h1, l0, l1;
                split1(acc[mt][nt][h2 * 2 + 0], h0, l0);
                split1(acc[mt][nt][h2 * 2 + 1], h1, l1);
                *(__nv_bfloat162*)&g_ch[o] = __nv_bfloat162{h0, h1};
                *(__nv_bfloat162*)&g_cl[o] = __nv_bfloat162{l0, l1};
            }
        }
}

// ---------------------------------------------------------------------------
// Launch. Inputs: qs ks vs mask Wq bq Wk bk Wv bv Wo bo.
// d_out: out [B,S,D] then attn [B,H,S,S].
// ---------------------------------------------------------------------------
extern "C" void kernel_launch(void* const* d_in, const int* in_sizes, int n_in,
                              void* d_out, int out_size)
{
    const float* qs = (const float*)d_in[0];
    const float* ks = (const float*)d_in[1];
    const float* vs = (const float*)d_in[2];
    const void*  mask = d_in[3];
    const float* Wq = (const float*)d_in[4];
    const float* bq = (const float*)d_in[5];
    const float* Wk = (const float*)d_in[6];
    const float* bk = (const float*)d_in[7];
    const float* Wv = (const float*)d_in[8];
    const float* bv = (const float*)d_in[9];
    const float* Wo = (const float*)d_in[10];
    const float* bo = (const float*)d_in[11];

    float* out  = (float*)d_out;
    float* attn = out + NIN;

    static int smem_set = 0;
    if (!smem_set) {
        cudaFuncSetAttribute(scores_kernel,
            cudaFuncAttributeMaxDynamicSharedMemorySize, 128 * 8 * 4 + 4 * 128 * 72 * 2);
        cudaFuncSetAttribute(ctx_kernel,
            cudaFuncAttributeMaxDynamicSharedMemorySize, 512 + 2 * 128 * 136 * 2 + 2 * 128 * 72 * 2);
        smem_set = 1;
    }

    __nv_bfloat16 *inh, *inl, *wh, *wl, *qh, *ql, *kh, *kl, *vh, *vl, *ch, *cl;
    cudaGetSymbolAddress((void**)&inh, g_inh);
    cudaGetSymbolAddress((void**)&inl, g_inl);
    cudaGetSymbolAddress((void**)&wh, g_wh);
    cudaGetSymbolAddress((void**)&wl, g_wl);
    cudaGetSymbolAddress((void**)&qh, g_qh);
    cudaGetSymbolAddress((void**)&ql, g_ql);
    cudaGetSymbolAddress((void**)&kh, g_kh);
    cudaGetSymbolAddress((void**)&kl, g_kl);
    cudaGetSymbolAddress((void**)&vh, g_vh);
    cudaGetSymbolAddress((void**)&vl, g_vl);
    cudaGetSymbolAddress((void**)&ch, g_ch);
    cudaGetSymbolAddress((void**)&cl, g_cl);

    detect_mask_kernel<<<1, 256>>>((const unsigned char*)mask);

    // Pre-split inputs and weights
    const int n4in = (int)(NIN / 4), n4w = (int)(NW / 4);
    split_kernel<<<n4in / 256, 256>>>((const float4*)qs,
        (__nv_bfloat162*)(inh + 0 * NIN), (__nv_bfloat162*)(inl + 0 * NIN), n4in);
    split_kernel<<<n4in / 256, 256>>>((const float4*)ks,
        (__nv_bfloat162*)(inh + 1 * NIN), (__nv_bfloat162*)(inl + 1 * NIN), n4in);
    split_kernel<<<n4in / 256, 256>>>((const float4*)vs,
        (__nv_bfloat162*)(inh + 2 * NIN), (__nv_bfloat162*)(inl + 2 * NIN), n4in);
    split_kernel<<<n4w / 256, 256>>>((const float4*)Wq,
        (__nv_bfloat162*)(wh + 0 * NW), (__nv_bfloat162*)(wl + 0 * NW), n4w);
    split_kernel<<<n4w / 256, 256>>>((const float4*)Wk,
        (__nv_bfloat162*)(wh + 1 * NW), (__nv_bfloat162*)(wl + 1 * NW), n4w);
    split_kernel<<<n4w / 256, 256>>>((const float4*)Wv,
        (__nv_bfloat162*)(wh + 2 * NW), (__nv_bfloat162*)(wl + 2 * NW), n4w);
    split_kernel<<<n4w / 256, 256>>>((const float4*)Wo,
        (__nv_bfloat162*)(wh + 3 * NW), (__nv_bfloat162*)(wl + 3 * NW), n4w);

    dim3 gProj(Dm / 128, (Bz * Sq) / 128);  // (8, 32)
    proj_gemm<0><<<gProj, 256>>>(inh + 0 * NIN, inl + 0 * NIN, wh + 0 * NW, wl + 0 * NW,
                                 bq, qh, ql, nullptr);
    proj_gemm<0><<<gProj, 256>>>(inh + 1 * NIN, inl + 1 * NIN, wh + 1 * NW, wl + 1 * NW,
                                 bk, kh, kl, nullptr);
    proj_gemm<0><<<gProj, 256>>>(inh + 2 * NIN, inl + 2 * NIN, wh + 2 * NW, wl + 2 * NW,
                                 bv, vh, vl, nullptr);

    scores_kernel<<<dim3(1, Sq / 128, BH), 256,
                    128 * 8 * 4 + 4 * 128 * 72 * 2>>>(mask, attn);

    ctx_kernel<<<dim3(1, Sq / 128, BH), 256,
                 512 + 2 * 128 * 136 * 2 + 2 * 128 * 72 * 2>>>(attn);

    proj_gemm<1><<<gProj, 256>>>(ch, cl, wh + 3 * NW, wl + 3 * NW,
                                 bo, nullptr, nullptr, out);
}

// round 4
// speedup vs baseline: 1.2278x; 1.2278x over previous
#include <cuda_runtime.h>
#include <cuda_bf16.h>
#include <stdint.h>
#include <math.h>

// Problem constants
#define Bz  2
#define Sq  2048
#define Dm  1024
#define Hn  16
#define DHd 64
#define BH  (Bz * Hn)

#define NIN ((size_t)Bz * Sq * Dm)    // 4194304
#define NW  ((size_t)Dm * Dm)         // 1048576
#define NQ  ((size_t)BH * Sq * DHd)   // 4194304
#define CLOG2E 1.4426950408889634f

// ---------------------------------------------------------------------------
// Scratch: pre-split bf16 hi/lo operands
// ---------------------------------------------------------------------------
__device__ __align__(256) __nv_bfloat16 g_inh[3 * NIN], g_inl[3 * NIN];
__device__ __align__(256) __nv_bfloat16 g_wh[4 * NW],  g_wl[4 * NW];
__device__ __align__(256) __nv_bfloat16 g_qh[NQ], g_ql[NQ];
__device__ __align__(256) __nv_bfloat16 g_kh[NQ], g_kl[NQ];
__device__ __align__(256) __nv_bfloat16 g_vh[NQ], g_vl[NQ];
__device__ __align__(256) __nv_bfloat16 g_ch[NIN], g_cl[NIN];
__device__ int g_mask_is_int;

// ---------------------------------------------------------------------------
// Helpers
// ---------------------------------------------------------------------------
__device__ __forceinline__ uint32_t smem_u32(const void* p) {
    return (uint32_t)__cvta_generic_to_shared(p);
}
__device__ __forceinline__ void ldm4(uint32_t* r, uint32_t a) {
    asm volatile("ldmatrix.sync.aligned.m8n8.x4.shared.b16 {%0,%1,%2,%3},[%4];"
                 : "=r"(r[0]), "=r"(r[1]), "=r"(r[2]), "=r"(r[3]) : "r"(a));
}
__device__ __forceinline__ void ldm4t(uint32_t* r, uint32_t a) {
    asm volatile("ldmatrix.sync.aligned.m8n8.x4.trans.shared.b16 {%0,%1,%2,%3},[%4];"
                 : "=r"(r[0]), "=r"(r[1]), "=r"(r[2]), "=r"(r[3]) : "r"(a));
}
__device__ __forceinline__ void mma_bf16(float* c, const uint32_t* a, const uint32_t* b) {
    asm volatile(
        "mma.sync.aligned.m16n8k16.row.col.f32.bf16.bf16.f32 "
        "{%0,%1,%2,%3},{%4,%5,%6,%7},{%8,%9},{%0,%1,%2,%3};"
        : "+f"(c[0]), "+f"(c[1]), "+f"(c[2]), "+f"(c[3])
        : "r"(a[0]), "r"(a[1]), "r"(a[2]), "r"(a[3]), "r"(b[0]), "r"(b[1]));
}
__device__ __forceinline__ void split1(float x, __nv_bfloat16& h, __nv_bfloat16& l) {
    h = __float2bfloat16(x);
    l = __float2bfloat16(x - __bfloat162float(h));
}

// ---------------------------------------------------------------------------
// Mask dtype detector
// ---------------------------------------------------------------------------
__global__ void detect_mask_kernel(const unsigned char* __restrict__ m) {
    __shared__ int any;
    if (threadIdx.x == 0) any = 0;
    __syncthreads();
    int local = 0;
    for (int i = threadIdx.x; i < Bz * Sq; i += blockDim.x)
        if ((i & 3) && m[i]) local = 1;
    if (local) atomicOr(&any, 1);
    __syncthreads();
    if (threadIdx.x == 0) g_mask_is_int = (any == 0) ? 1 : 0;
}

// ---------------------------------------------------------------------------
// Pre-split f32 -> (hi, lo) bf16
// ---------------------------------------------------------------------------
__global__ void split_kernel(const float4* __restrict__ src,
                             __nv_bfloat162* __restrict__ dh,
                             __nv_bfloat162* __restrict__ dl, int n4)
{
    int i = blockIdx.x * blockDim.x + threadIdx.x;
    if (i >= n4) return;
    float4 v = src[i];
    __nv_bfloat16 hx, hy, hz, hw, lx, ly, lz, lw;
    split1(v.x, hx, lx); split1(v.y, hy, ly);
    split1(v.z, hz, lz); split1(v.w, hw, lw);
    dh[2 * i]     = __nv_bfloat162{hx, hy};
    dh[2 * i + 1] = __nv_bfloat162{hz, hw};
    dl[2 * i]     = __nv_bfloat162{lx, ly};
    dl[2 * i + 1] = __nv_bfloat162{lz, lw};
}

// ---------------------------------------------------------------------------
// Projection GEMM, pre-split operands, 128x128x32 tiles, 8 warps.
// MODE 0: head-split epilogue -> split bf16; MODE 1: plain f32 epilogue.
// ---------------------------------------------------------------------------
template <int MODE>
__global__ void __launch_bounds__(256) proj_gemm(
    const __nv_bfloat16* __restrict__ Ahg, const __nv_bfloat16* __restrict__ Alg,
    const __nv_bfloat16* __restrict__ Bhg, const __nv_bfloat16* __restrict__ Blg,
    const float* __restrict__ bias,
    __nv_bfloat16* __restrict__ Ch, __nv_bfloat16* __restrict__ Cl,
    float* __restrict__ Cf)
{
    constexpr int SA = 40, SB = 136;
    __shared__ __nv_bfloat16 Ah[128 * SA], Al[128 * SA];
    __shared__ __nv_bfloat16 Bh[32 * SB],  Bl[32 * SB];

    const int tid = threadIdx.x, lane = tid & 31, warp = tid >> 5;
    const int wm = (warp >> 2) * 64;
    const int wn = (warp & 3) * 32;
    const int bm = blockIdx.y * 128;
    const int bn = blockIdx.x * 128;

    float acc[4][4][4];
#pragma unroll
    for (int i = 0; i < 4; i++)
#pragma unroll
        for (int j = 0; j < 4; j++)
#pragma unroll
            for (int q = 0; q < 4; q++) acc[i][j][q] = 0.f;

    const uint32_t aH = smem_u32(Ah), aL = smem_u32(Al);
    const uint32_t bH = smem_u32(Bh), bL = smem_u32(Bl);

    for (int k0 = 0; k0 < Dm; k0 += 32) {
#pragma unroll
        for (int r = 0; r < 2; r++) {
            const int idx = tid + r * 256;
            const int m = idx >> 2, c8 = (idx & 3) * 8;
            *(uint4*)&Ah[m * SA + c8] = *(const uint4*)(Ahg + (size_t)(bm + m) * Dm + k0 + c8);
            *(uint4*)&Al[m * SA + c8] = *(const uint4*)(Alg + (size_t)(bm + m) * Dm + k0 + c8);
        }
#pragma unroll
        for (int r = 0; r < 2; r++) {
            const int idx = tid + r * 256;
            const int kr = idx >> 4, n8 = (idx & 15) * 8;
            *(uint4*)&Bh[kr * SB + n8] = *(const uint4*)(Bhg + (size_t)(k0 + kr) * Dm + bn + n8);
            *(uint4*)&Bl[kr * SB + n8] = *(const uint4*)(Blg + (size_t)(k0 + kr) * Dm + bn + n8);
        }
        __syncthreads();

#pragma unroll
        for (int kk = 0; kk < 32; kk += 16) {
            uint32_t ah[4][4], al[4][4];
            const int arow = wm + (lane & 7) + ((lane >> 3) & 1) * 8;
            const int acol = kk + (lane >> 4) * 8;
#pragma unroll
            for (int mt = 0; mt < 4; mt++) {
                const uint32_t off = (uint32_t)(((arow + mt * 16) * SA + acol) * 2);
                ldm4(ah[mt], aH + off);
                ldm4(al[mt], aL + off);
            }
            uint32_t bh[4][2], bl[4][2];
            const int brow = kk + (lane & 7) + ((lane >> 3) & 1) * 8;
#pragma unroll
            for (int sp = 0; sp < 2; sp++) {
                const int bcol = wn + sp * 16 + (lane >> 4) * 8;
                const uint32_t off = (uint32_t)((brow * SB + bcol) * 2);
                uint32_t t[4];
                ldm4t(t, bH + off);
                bh[2 * sp][0] = t[0]; bh[2 * sp][1] = t[1];
                bh[2 * sp + 1][0] = t[2]; bh[2 * sp + 1][1] = t[3];
                ldm4t(t, bL + off);
                bl[2 * sp][0] = t[0]; bl[2 * sp][1] = t[1];
                bl[2 * sp + 1][0] = t[2]; bl[2 * sp + 1][1] = t[3];
            }
#pragma unroll
            for (int mt = 0; mt < 4; mt++)
#pragma unroll
                for (int nt = 0; nt < 4; nt++) {
                    mma_bf16(acc[mt][nt], ah[mt], bh[nt]);
                    mma_bf16(acc[mt][nt], ah[mt], bl[nt]);
                    mma_bf16(acc[mt][nt], al[mt], bh[nt]);
                }
        }
        __syncthreads();
    }

    const int g = lane >> 2, t2 = (lane & 3) * 2;
#pragma unroll
    for (int mt = 0; mt < 4; mt++)
#pragma unroll
        for (int nt = 0; nt < 4; nt++) {
            const int col = bn + wn + nt * 8 + t2;
#pragma unroll
            for (int h2 = 0; h2 < 2; h2++) {
                const int row = bm + wm + mt * 16 + g + h2 * 8;
                float c0 = acc[mt][nt][h2 * 2 + 0] + bias[col];
                float c1 = acc[mt][nt][h2 * 2 + 1] + bias[col + 1];
                if (MODE == 0) {
                    const int bb = row >> 11, ss = row & (Sq - 1);
                    const int hh = col >> 6,  dh = col & (DHd - 1);
                    const size_t o = (((size_t)(bb * Hn + hh)) * Sq + ss) * DHd + dh;
                    __nv_bfloat16 h0, h1, l0, l1;
                    split1(c0, h0, l0); split1(c1, h1, l1);
                    *(__nv_bfloat162*)&Ch[o] = __nv_bfloat162{h0, h1};
                    *(__nv_bfloat162*)&Cl[o] = __nv_bfloat162{l0, l1};
                } else {
                    *(float2*)(Cf + (size_t)row * Dm + col) = make_float2(c0, c1);
                }
            }
        }
}

// ---------------------------------------------------------------------------
// Scores: R2-style tiling, grid (16,16,32), copy fills from pre-split q/k.
// Q*K^T * 0.125, mask -> -inf, raw f32 into attn region.
// ---------------------------------------------------------------------------
__global__ void __launch_bounds__(256) scores_kernel(
    const void* __restrict__ mask, float* __restrict__ attn)
{
    constexpr int SA = 40, SB = 40;
    __shared__ __nv_bfloat16 Ah[128 * SA], Al[128 * SA];
    __shared__ __nv_bfloat16 Bh[128 * SB], Bl[128 * SB];

    const int z = blockIdx.z, zb = z / Hn;
    const __nv_bfloat16* qh = g_qh + (size_t)z * Sq * DHd;
    const __nv_bfloat16* ql = g_ql + (size_t)z * Sq * DHd;
    const __nv_bfloat16* kh = g_kh + (size_t)z * Sq * DHd;
    const __nv_bfloat16* kl = g_kl + (size_t)z * Sq * DHd;

    const int tid = threadIdx.x, lane = tid & 31, warp = tid >> 5;
    const int wm = (warp >> 2) * 64;
    const int wn = (warp & 3) * 32;
    const int bm = blockIdx.y * 128;
    const int bn = blockIdx.x * 128;

    float acc[4][4][4];
#pragma unroll
    for (int i = 0; i < 4; i++)
#pragma unroll
        for (int j = 0; j < 4; j++)
#pragma unroll
            for (int q = 0; q < 4; q++) acc[i][j][q] = 0.f;

    const uint32_t aH = smem_u32(Ah), aL = smem_u32(Al);
    const uint32_t bH = smem_u32(Bh), bL = smem_u32(Bl);

    for (int k0 = 0; k0 < DHd; k0 += 32) {
#pragma unroll
        for (int r = 0; r < 2; r++) {
            const int idx = tid + r * 256;
            const int m = idx >> 2, c8 = (idx & 3) * 8;
            *(uint4*)&Ah[m * SA + c8] = *(const uint4*)(qh + (size_t)(bm + m) * DHd + k0 + c8);
            *(uint4*)&Al[m * SA + c8] = *(const uint4*)(ql + (size_t)(bm + m) * DHd + k0 + c8);
            *(uint4*)&Bh[m * SB + c8] = *(const uint4*)(kh + (size_t)(bn + m) * DHd + k0 + c8);
            *(uint4*)&Bl[m * SB + c8] = *(const uint4*)(kl + (size_t)(bn + m) * DHd + k0 + c8);
        }
        __syncthreads();

#pragma unroll
        for (int kk = 0; kk < 32; kk += 16) {
            uint32_t ah[4][4], al[4][4];
            const int arow = wm + (lane & 7) + ((lane >> 3) & 1) * 8;
            const int acol = kk + (lane >> 4) * 8;
#pragma unroll
            for (int mt = 0; mt < 4; mt++) {
                const uint32_t off = (uint32_t)(((arow + mt * 16) * SA + acol) * 2);
                ldm4(ah[mt], aH + off);
                ldm4(al[mt], aL + off);
            }
            uint32_t bh[4][2], bl[4][2];
#pragma unroll
            for (int sp = 0; sp < 2; sp++) {
                const int brow = wn + sp * 16 + (lane & 7) + ((lane >> 3) & 1) * 8;
                const int bcol = kk + (lane >> 4) * 8;
                const uint32_t off = (uint32_t)((brow * SB + bcol) * 2);
                uint32_t t[4];
                ldm4(t, bH + off);
                bh[2 * sp][0] = t[0]; bh[2 * sp + 1][0] = t[1];
                bh[2 * sp][1] = t[2]; bh[2 * sp + 1][1] = t[3];
                ldm4(t, bL + off);
                bl[2 * sp][0] = t[0]; bl[2 * sp + 1][0] = t[1];
                bl[2 * sp][1] = t[2]; bl[2 * sp + 1][1] = t[3];
            }
#pragma unroll
            for (int mt = 0; mt < 4; mt++)
#pragma unroll
                for (int nt = 0; nt < 4; nt++) {
                    mma_bf16(acc[mt][nt], ah[mt], bh[nt]);
                    mma_bf16(acc[mt][nt], ah[mt], bl[nt]);
                    mma_bf16(acc[mt][nt], al[mt], bh[nt]);
                }
        }
        __syncthreads();
    }

    const int g = lane >> 2, t2 = (lane & 3) * 2;
    const int mint = g_mask_is_int;
    const float NEG_INF = __int_as_float(0xff800000);
#pragma unroll
    for (int nt = 0; nt < 4; nt++) {
        const int col = bn + wn + nt * 8 + t2;
        bool m0, m1;
        if (mint) {
            m0 = ((const int*)mask)[zb * Sq + col] != 0;
            m1 = ((const int*)mask)[zb * Sq + col + 1] != 0;
        } else {
            m0 = ((const unsigned char*)mask)[zb * Sq + col] != 0;
            m1 = ((const unsigned char*)mask)[zb * Sq + col + 1] != 0;
        }
#pragma unroll
        for (int mt = 0; mt < 4; mt++)
#pragma unroll
            for (int h2 = 0; h2 < 2; h2++) {
                const int row = bm + wm + mt * 16 + g + h2 * 8;
                float v0 = m0 ? acc[mt][nt][h2 * 2 + 0] * 0.125f : NEG_INF;
                float v1 = m1 ? acc[mt][nt][h2 * 2 + 1] * 0.125f : NEG_INF;
                *(float2*)(attn + ((size_t)z * Sq + row) * Sq + col) = make_float2(v0, v1);
            }
    }
}

// ---------------------------------------------------------------------------
// In-place row softmax over S=2048 (proven R2 version)
// ---------------------------------------------------------------------------
__global__ void __launch_bounds__(256) softmax_kernel(float* __restrict__ attn)
{
    const size_t row = blockIdx.x;
    float4* p = (float4*)(attn + row * Sq);
    const int tid = threadIdx.x;

    float4 v0 = p[tid];
    float4 v1 = p[tid + 256];

    float m = fmaxf(fmaxf(fmaxf(v0.x, v0.y), fmaxf(v0.z, v0.w)),
                    fmaxf(fmaxf(v1.x, v1.y), fmaxf(v1.z, v1.w)));
#pragma unroll
    for (int o = 16; o; o >>= 1) m = fmaxf(m, __shfl_xor_sync(~0u, m, o));

    __shared__ float sred[8];
    if ((tid & 31) == 0) sred[tid >> 5] = m;
    __syncthreads();
    if (tid < 32) {
        float t = (tid < 8) ? sred[tid] : __int_as_float(0xff800000);
#pragma unroll
        for (int o = 4; o; o >>= 1) t = fmaxf(t, __shfl_xor_sync(~0u, t, o));
        if (tid == 0) sred[0] = t;
    }
    __syncthreads();
    m = sred[0];
    __syncthreads();

    float e[8];
    e[0] = expf(v0.x - m); e[1] = expf(v0.y - m);
    e[2] = expf(v0.z - m); e[3] = expf(v0.w - m);
    e[4] = expf(v1.x - m); e[5] = expf(v1.y - m);
    e[6] = expf(v1.z - m); e[7] = expf(v1.w - m);
    float s = e[0] + e[1] + e[2] + e[3] + e[4] + e[5] + e[6] + e[7];
#pragma unroll
    for (int o = 16; o; o >>= 1) s += __shfl_xor_sync(~0u, s, o);
    if ((tid & 31) == 0) sred[tid >> 5] = s;
    __syncthreads();
    if (tid < 32) {
        float t = (tid < 8) ? sred[tid] : 0.f;
#pragma unroll
        for (int o = 4; o; o >>= 1) t += __shfl_xor_sync(~0u, t, o);
        if (tid == 0) sred[0] = t;
    }
    __syncthreads();
    const float inv = 1.f / sred[0];

    v0 = make_float4(e[0] * inv, e[1] * inv, e[2] * inv, e[3] * inv);
    v1 = make_float4(e[4] * inv, e[5] * inv, e[6] * inv, e[7] * inv);
    p[tid]       = v0;
    p[tid + 256] = v1;
}

// ---------------------------------------------------------------------------
// Ctx: R2-style tiling, grid (1,16,32). P split on fill (f32 attn), V copy
// from pre-split; epilogue writes split bf16 ctx in [B,S,D].
// ---------------------------------------------------------------------------
__global__ void __launch_bounds__(256) ctx_kernel(const float* __restrict__ attn)
{
    constexpr int SA = 40, SB = 72;
    __shared__ __nv_bfloat16 Ah[128 * SA], Al[128 * SA];
    __shared__ __nv_bfloat16 Bh[32 * SB],  Bl[32 * SB];

    const int z = blockIdx.z, zb = z / Hn, zh = z % Hn;
    const float* P = attn + (size_t)z * Sq * Sq;
    const __nv_bfloat16* vh = g_vh + (size_t)z * Sq * DHd;
    const __nv_bfloat16* vl = g_vl + (size_t)z * Sq * DHd;
    const int bm = blockIdx.y * 128;

    const int tid = threadIdx.x, lane = tid & 31, warp = tid >> 5;
    const int wm = (warp >> 2) * 64;
    const int wn = (warp & 3) * 16;

    float acc[4][2][4];
#pragma unroll
    for (int i = 0; i < 4; i++)
#pragma unroll
        for (int j = 0; j < 2; j++)
#pragma unroll
            for (int q = 0; q < 4; q++) acc[i][j][q] = 0.f;

    const uint32_t aH = smem_u32(Ah), aL = smem_u32(Al);
    const uint32_t bH = smem_u32(Bh), bL = smem_u32(Bl);

    for (int k0 = 0; k0 < Sq; k0 += 32) {
        // P fill: f32 -> split bf16
#pragma unroll
        for (int r = 0; r < 4; r++) {
            const int idx = tid + r * 256;
            const int m = idx >> 3, kq = (idx & 7) * 4;
            float4 v = *(const float4*)(P + (size_t)(bm + m) * Sq + k0 + kq);
            __nv_bfloat16 h0, h1, h2, h3, l0, l1, l2, l3;
            split1(v.x, h0, l0); split1(v.y, h1, l1);
            split1(v.z, h2, l2); split1(v.w, h3, l3);
            *(__nv_bfloat162*)&Ah[m * SA + kq]     = __nv_bfloat162{h0, h1};
            *(__nv_bfloat162*)&Ah[m * SA + kq + 2] = __nv_bfloat162{h2, h3};
            *(__nv_bfloat162*)&Al[m * SA + kq]     = __nv_bfloat162{l0, l1};
            *(__nv_bfloat162*)&Al[m * SA + kq + 2] = __nv_bfloat162{l2, l3};
        }
        // V fill: pure copy
        {
            const int kr = tid >> 3, n8 = (tid & 7) * 8;
            *(uint4*)&Bh[kr * SB + n8] = *(const uint4*)(vh + (size_t)(k0 + kr) * DHd + n8);
            *(uint4*)&Bl[kr * SB + n8] = *(const uint4*)(vl + (size_t)(k0 + kr) * DHd + n8);
        }
        __syncthreads();

#pragma unroll
        for (int kk = 0; kk < 32; kk += 16) {
            uint32_t ah[4][4], al[4][4];
            const int arow = wm + (lane & 7) + ((lane >> 3) & 1) * 8;
            const int acol = kk + (lane >> 4) * 8;
#pragma unroll
            for (int mt = 0; mt < 4; mt++) {
                const uint32_t off = (uint32_t)(((arow + mt * 16) * SA + acol) * 2);
                ldm4(ah[mt], aH + off);
                ldm4(al[mt], aL + off);
            }
            uint32_t bh[2][2], bl[2][2];
            {
                const int brow = kk + (lane & 7) + ((lane >> 3) & 1) * 8;
                const int bcol = wn + (lane >> 4) * 8;
                const uint32_t off = (uint32_t)((brow * SB + bcol) * 2);
                uint32_t t[4];
                ldm4t(t, bH + off);
                bh[0][0] = t[0]; bh[0][1] = t[1];
                bh[1][0] = t[2]; bh[1][1] = t[3];
                ldm4t(t, bL + off);
                bl[0][0] = t[0]; bl[0][1] = t[1];
                bl[1][0] = t[2]; bl[1][1] = t[3];
            }
#pragma unroll
            for (int mt = 0; mt < 4; mt++)
#pragma unroll
                for (int nt = 0; nt < 2; nt++) {
                    mma_bf16(acc[mt][nt], ah[mt], bh[nt]);
                    mma_bf16(acc[mt][nt], ah[mt], bl[nt]);
                    mma_bf16(acc[mt][nt], al[mt], bh[nt]);
                }
        }
        __syncthreads();
    }

    const int g = lane >> 2, t2 = (lane & 3) * 2;
#pragma unroll
    for (int mt = 0; mt < 4; mt++)
#pragma unroll
        for (int nt = 0; nt < 2; nt++) {
            const int col = wn + nt * 8 + t2;
#pragma unroll
            for (int h2 = 0; h2 < 2; h2++) {
                const int row = bm + wm + mt * 16 + g + h2 * 8;
                const size_t o = ((size_t)zb * Sq + row) * Dm + zh * DHd + col;
                __nv_bfloat16 h0, h1, l0, l1;
                split1(acc[mt][nt][h2 * 2 + 0], h0, l0);
                split1(acc[mt][nt][h2 * 2 + 1], h1, l1);
                *(__nv_bfloat162*)&g_ch[o] = __nv_bfloat162{h0, h1};
                *(__nv_bfloat162*)&g_cl[o] = __nv_bfloat162{l0, l1};
            }
        }
}

// ---------------------------------------------------------------------------
// Launch. Inputs: qs ks vs mask Wq bq Wk bk Wv bv Wo bo.
// d_out: out [B,S,D] then attn [B,H,S,S].
// ---------------------------------------------------------------------------
extern "C" void kernel_launch(void* const* d_in, const int* in_sizes, int n_in,
                              void* d_out, int out_size)
{
    const float* qs = (const float*)d_in[0];
    const float* ks = (const float*)d_in[1];
    const float* vs = (const float*)d_in[2];
    const void*  mask = d_in[3];
    const float* Wq = (const float*)d_in[4];
    const float* bq = (const float*)d_in[5];
    const float* Wk = (const float*)d_in[6];
    const float* bk = (const float*)d_in[7];
    const float* Wv = (const float*)d_in[8];
    const float* bv = (const float*)d_in[9];
    const float* Wo = (const float*)d_in[10];
    const float* bo = (const float*)d_in[11];

    float* out  = (float*)d_out;
    float* attn = out + NIN;

    __nv_bfloat16 *inh, *inl, *wh, *wl, *qh, *ql, *kh, *kl, *vh, *vl, *ch, *cl;
    cudaGetSymbolAddress((void**)&inh, g_inh);
    cudaGetSymbolAddress((void**)&inl, g_inl);
    cudaGetSymbolAddress((void**)&wh, g_wh);
    cudaGetSymbolAddress((void**)&wl, g_wl);
    cudaGetSymbolAddress((void**)&qh, g_qh);
    cudaGetSymbolAddress((void**)&ql, g_ql);
    cudaGetSymbolAddress((void**)&kh, g_kh);
    cudaGetSymbolAddress((void**)&kl, g_kl);
    cudaGetSymbolAddress((void**)&vh, g_vh);
    cudaGetSymbolAddress((void**)&vl, g_vl);
    cudaGetSymbolAddress((void**)&ch, g_ch);
    cudaGetSymbolAddress((void**)&cl, g_cl);

    detect_mask_kernel<<<1, 256>>>((const unsigned char*)mask);

    const int n4in = (int)(NIN / 4), n4w = (int)(NW / 4);
    split_kernel<<<n4in / 256, 256>>>((const float4*)qs,
        (__nv_bfloat162*)(inh + 0 * NIN), (__nv_bfloat162*)(inl + 0 * NIN), n4in);
    split_kernel<<<n4in / 256, 256>>>((const float4*)ks,
        (__nv_bfloat162*)(inh + 1 * NIN), (__nv_bfloat162*)(inl + 1 * NIN), n4in);
    split_kernel<<<n4in / 256, 256>>>((const float4*)vs,
        (__nv_bfloat162*)(inh + 2 * NIN), (__nv_bfloat162*)(inl + 2 * NIN), n4in);
    split_kernel<<<n4w / 256, 256>>>((const float4*)Wq,
        (__nv_bfloat162*)(wh + 0 * NW), (__nv_bfloat162*)(wl + 0 * NW), n4w);
    split_kernel<<<n4w / 256, 256>>>((const float4*)Wk,
        (__nv_bfloat162*)(wh + 1 * NW), (__nv_bfloat162*)(wl + 1 * NW), n4w);
    split_kernel<<<n4w / 256, 256>>>((const float4*)Wv,
        (__nv_bfloat162*)(wh + 2 * NW), (__nv_bfloat162*)(wl + 2 * NW), n4w);
    split_kernel<<<n4w / 256, 256>>>((const float4*)Wo,
        (__nv_bfloat162*)(wh + 3 * NW), (__nv_bfloat162*)(wl + 3 * NW), n4w);

    dim3 gProj(Dm / 128, (Bz * Sq) / 128);  // (8, 32)
    proj_gemm<0><<<gProj, 256>>>(inh + 0 * NIN, inl + 0 * NIN, wh + 0 * NW, wl + 0 * NW,
                                 bq, qh, ql, nullptr);
    proj_gemm<0><<<gProj, 256>>>(inh + 1 * NIN, inl + 1 * NIN, wh + 1 * NW, wl + 1 * NW,
                                 bk, kh, kl, nullptr);
    proj_gemm<0><<<gProj, 256>>>(inh + 2 * NIN, inl + 2 * NIN, wh + 2 * NW, wl + 2 * NW,
                                 bv, vh, vl, nullptr);

    scores_kernel<<<dim3(Sq / 128, Sq / 128, BH), 256>>>(mask, attn);

    softmax_kernel<<<(unsigned)((size_t)BH * Sq), 256>>>(attn);

    ctx_kernel<<<dim3(1, Sq / 128, BH), 256>>>(attn);

    proj_gemm<1><<<gProj, 256>>>(ch, cl, wh + 3 * NW, wl + 3 * NW,
                                 bo, nullptr, nullptr, out);
}